// round 11
// baseline (speedup 1.0000x reference)
#include <cuda_runtime.h>
#include <cuda_bf16.h>
#include <math.h>
#include <stdint.h>

#define NNODES 50000
#define NEDG   400000
#define ETOT   450000
#define WID    256
#define NG     256
#define NPAD   50048        // 391 * 128
#define MTILES 391
#define DCAP   256

// ---------------- scratch globals ----------------
__device__ float g_h[(size_t)NNODES * WID];
__device__ float g_als[NNODES * 4];
__device__ float g_ald[NNODES * 4];
__device__ float g_esc[(size_t)ETOT * 4];    // fallback only (deg > DCAP)
__device__ int   g_dst[ETOT];
__device__ int   g_srcE[ETOT];
__device__ int   g_scsr[ETOT];
__device__ int   g_deg[NNODES];
__device__ int   g_rowptr[NNODES + 1];
__device__ int   g_cursor[NNODES];
__device__ int   g_i64flag;
__device__ int   g_incl[NNODES];
__device__ int   g_bsum[64];
__device__ int   g_boff[64];
// bf16 split operands (zero-init covers M padding)
__device__ __align__(16) __nv_bfloat16 g_Ahi[(size_t)NPAD * WID];
__device__ __align__(16) __nv_bfloat16 g_Alo[(size_t)NPAD * WID];
__device__ __align__(16) __nv_bfloat16 g_Bhi[WID * WID];   // [N=256][K]
__device__ __align__(16) __nv_bfloat16 g_Blo[WID * WID];

// ---------------- helpers ----------------
__device__ __forceinline__ uint32_t smem_u32(const void* p) {
    uint32_t a;
    asm("{ .reg .u64 t; cvta.to.shared.u64 t, %1; cvt.u32.u64 %0, t; }" : "=r"(a) : "l"(p));
    return a;
}
__device__ __forceinline__ void cp16(uint32_t s, const void* g) {
    asm volatile("cp.async.cg.shared.global [%0], [%1], 16;" :: "r"(s), "l"(g));
}
#define CP_COMMIT()  asm volatile("cp.async.commit_group;" ::: "memory")
#define CP_WAIT(n)   asm volatile("cp.async.wait_group %0;" :: "n"(n) : "memory")

__device__ __forceinline__ void mma16816(float* d, const uint32_t* a, const uint32_t* b) {
    asm volatile(
        "mma.sync.aligned.m16n8k16.row.col.f32.bf16.bf16.f32 "
        "{%0,%1,%2,%3}, {%4,%5,%6,%7}, {%8,%9}, {%0,%1,%2,%3};"
        : "+f"(d[0]), "+f"(d[1]), "+f"(d[2]), "+f"(d[3])
        : "r"(a[0]), "r"(a[1]), "r"(a[2]), "r"(a[3]), "r"(b[0]), "r"(b[1]));
}
__device__ __forceinline__ void ldsm_x4(uint32_t* r, uint32_t addr) {
    asm volatile("ldmatrix.sync.aligned.m8n8.x4.shared.b16 {%0,%1,%2,%3}, [%4];"
        : "=r"(r[0]), "=r"(r[1]), "=r"(r[2]), "=r"(r[3]) : "r"(addr));
}

// ---------------- dtype probe + clear deg ----------------
__global__ void k_probe_clear(const int* __restrict__ ei32) {
    int i = blockIdx.x * blockDim.x + threadIdx.x;
    if (i < NNODES) g_deg[i] = 0;
    if (i == 0) {
        int allzero = 1;
#pragma unroll
        for (int j = 0; j < 8; j++) allzero &= (ei32[2 * j + 1] == 0);
        g_i64flag = allzero;
    }
}

// ---------------- CSR build ----------------
__global__ void k_count(const void* __restrict__ ei) {
    int i = blockIdx.x * blockDim.x + threadIdx.x;
    if (i >= ETOT) return;
    int s, d;
    if (i < NEDG) {
        if (g_i64flag) {
            const long long* p = (const long long*)ei;
            s = (int)p[i]; d = (int)p[NEDG + i];
        } else {
            const int* p = (const int*)ei;
            s = p[i]; d = p[NEDG + i];
        }
    } else {
        s = i - NEDG; d = s;
    }
    g_srcE[i] = s;
    g_dst[i] = d;
    atomicAdd(&g_deg[d], 1);
}

__global__ __launch_bounds__(1024) void k_scan_blk() {
    __shared__ int wsum[32];
    int tid = threadIdx.x, lane = tid & 31, w = tid >> 5;
    int i = blockIdx.x * 1024 + tid;
    int v = (i < NNODES) ? g_deg[i] : 0;
    int x = v;
#pragma unroll
    for (int o = 1; o < 32; o <<= 1) {
        int t = __shfl_up_sync(0xffffffffu, x, o);
        if (lane >= o) x += t;
    }
    if (lane == 31) wsum[w] = x;
    __syncthreads();
    if (w == 0) {
        int s = wsum[lane];
#pragma unroll
        for (int o = 1; o < 32; o <<= 1) {
            int t = __shfl_up_sync(0xffffffffu, s, o);
            if (lane >= o) s += t;
        }
        wsum[lane] = s;
    }
    __syncthreads();
    int incl = x + (w ? wsum[w - 1] : 0);
    if (i < NNODES) g_incl[i] = incl;
    if (tid == 1023) g_bsum[blockIdx.x] = incl;
}

// 64-thread shfl scan over block sums (exclusive)
__global__ void k_scan_top(int nb) {
    __shared__ int ws[2];
    int tid = threadIdx.x, lane = tid & 31, wi = tid >> 5;
    int v = (tid < nb) ? g_bsum[tid] : 0;
    int x = v;
#pragma unroll
    for (int o = 1; o < 32; o <<= 1) {
        int t = __shfl_up_sync(0xffffffffu, x, o);
        if (lane >= o) x += t;
    }
    if (lane == 31) ws[wi] = x;
    __syncthreads();
    int incl = x + ((wi == 1) ? ws[0] : 0);
    if (tid < nb) g_boff[tid] = incl - v;
}

__global__ void k_scan_fix() {
    int i = blockIdx.x * blockDim.x + threadIdx.x;
    if (i >= NNODES) return;
    int incl = g_incl[i] + g_boff[i >> 10];
    g_rowptr[i + 1] = incl;
    g_cursor[i] = incl - g_deg[i];
    if (i == 0) g_rowptr[0] = 0;
}

__global__ void k_fill() {
    int i = blockIdx.x * blockDim.x + threadIdx.x;
    if (i >= ETOT) return;
    int p = atomicAdd(&g_cursor[g_dst[i]], 1);
    g_scsr[p] = g_srcE[i];
}

// ---------------- fp32 -> bf16 hi/lo (layer 0; also zeroes g_als/ald) -------
__global__ void k_splitA(const float* __restrict__ in, int n4) {
    int i = blockIdx.x * blockDim.x + threadIdx.x;
    if (i < NNODES) {
        float4 z = make_float4(0.f, 0.f, 0.f, 0.f);
        ((float4*)g_als)[i] = z;
        ((float4*)g_ald)[i] = z;
    }
    if (i >= n4) return;
    float4 v = *(const float4*)(in + (size_t)i * 4);
    __nv_bfloat16 hx = __float2bfloat16(v.x), hy = __float2bfloat16(v.y);
    __nv_bfloat16 hz = __float2bfloat16(v.z), hw = __float2bfloat16(v.w);
    __nv_bfloat16 lx = __float2bfloat16(v.x - __bfloat162float(hx));
    __nv_bfloat16 ly = __float2bfloat16(v.y - __bfloat162float(hy));
    __nv_bfloat16 lz = __float2bfloat16(v.z - __bfloat162float(hz));
    __nv_bfloat16 lw = __float2bfloat16(v.w - __bfloat162float(hw));
    __nv_bfloat162* ph = (__nv_bfloat162*)g_Ahi + (size_t)i * 2;
    __nv_bfloat162* pl = (__nv_bfloat162*)g_Alo + (size_t)i * 2;
    ph[0] = __nv_bfloat162(hx, hy); ph[1] = __nv_bfloat162(hz, hw);
    pl[0] = __nv_bfloat162(lx, ly); pl[1] = __nv_bfloat162(lz, lw);
}

// W split for layers 1/2 — also clears g_als/g_ald for the next fused GEMM
__global__ void k_splitW(const float* __restrict__ W, int K) {
    int i = blockIdx.x * blockDim.x + threadIdx.x;
    if (i < NNODES) {
        float4 z = make_float4(0.f, 0.f, 0.f, 0.f);
        ((float4*)g_als)[i] = z;
        ((float4*)g_ald)[i] = z;
    }
    if (i >= K * WID) return;
    int k = i >> 8, n = i & 255;
    float v = W[i];
    __nv_bfloat16 h = __float2bfloat16(v);
    __nv_bfloat16 l = __float2bfloat16(v - __bfloat162float(h));
    g_Bhi[n * K + k] = h;
    g_Blo[n * K + k] = l;
}

// W split for layer 0 (no clear — splitA does it)
__global__ void k_splitW0(const float* __restrict__ W, int K) {
    int i = blockIdx.x * blockDim.x + threadIdx.x;
    if (i >= K * WID) return;
    int k = i >> 8, n = i & 255;
    float v = W[i];
    __nv_bfloat16 h = __float2bfloat16(v);
    __nv_bfloat16 l = __float2bfloat16(v - __bfloat162float(h));
    g_Bhi[n * K + k] = h;
    g_Blo[n * K + k] = l;
}

// ---------------- HMMA GEMM + fused attention epilogue ----------------
#define ROWB2  80
#define OFF_AH 0
#define OFF_AL 10240
#define OFF_BH 20480
#define OFF_BL 30720
#define STG2   40960
#define GSMEM2 81920

__device__ __forceinline__ void load_stage2(uint32_t sb, int bm, int bn, int K,
                                            int k0, int tid) {
#pragma unroll
    for (int i = 0; i < 2; i++) {
        int idx = tid + i * 256;
        int row = idx >> 2, seg = idx & 3;
        uint32_t so = row * ROWB2 + seg * 16;
        size_t ga = (size_t)(bm + row) * K + k0 + seg * 8;
        size_t gb = (size_t)(bn + row) * K + k0 + seg * 8;
        cp16(sb + OFF_AH + so, g_Ahi + ga);
        cp16(sb + OFF_AL + so, g_Alo + ga);
        cp16(sb + OFF_BH + so, g_Bhi + gb);
        cp16(sb + OFF_BL + so, g_Blo + gb);
    }
}

__global__ __launch_bounds__(256, 2) void k_gemm_mma(int K,
        const float* __restrict__ asrc, const float* __restrict__ adst) {
    extern __shared__ char smem[];
    uint32_t sb = smem_u32(smem);
    int tid = threadIdx.x, lane = tid & 31, w = tid >> 5;
    int bm = blockIdx.x * 128, bn = blockIdx.y * 128;
    int wm = (w >> 2) * 64, wn = (w & 3) * 32;

    float acc[4][4][4];
#pragma unroll
    for (int mt = 0; mt < 4; mt++)
#pragma unroll
        for (int nt = 0; nt < 4; nt++)
#pragma unroll
            for (int j = 0; j < 4; j++) acc[mt][nt][j] = 0.f;

    uint32_t aoff = (uint32_t)(wm + (lane & 15)) * ROWB2 + (lane >> 4) * 16;
    uint32_t boff = (uint32_t)(wn + ((lane >> 4) & 1) * 8 + (lane & 7)) * ROWB2
                  + ((lane >> 3) & 1) * 16;

    const int nc = K >> 5;
    load_stage2(sb, bm, bn, K, 0, tid);
    CP_COMMIT();

    for (int kc = 0; kc < nc; kc++) {
        if (kc + 1 < nc) {
            load_stage2(sb + ((kc + 1) & 1) * STG2, bm, bn, K, (kc + 1) << 5, tid);
            CP_COMMIT();
            CP_WAIT(1);
        } else {
            CP_WAIT(0);
        }
        __syncthreads();
        uint32_t st = sb + (kc & 1) * STG2;
#pragma unroll
        for (int ks = 0; ks < 2; ks++) {
            uint32_t kb = ks * 32;
            uint32_t ah[4][4], al[4][4];
#pragma unroll
            for (int mt = 0; mt < 4; mt++) {
                ldsm_x4(ah[mt], st + OFF_AH + aoff + mt * 16 * ROWB2 + kb);
                ldsm_x4(al[mt], st + OFF_AL + aoff + mt * 16 * ROWB2 + kb);
            }
#pragma unroll
            for (int p = 0; p < 2; p++) {
                uint32_t bh[4], bl[4];
                ldsm_x4(bh, st + OFF_BH + boff + p * 16 * ROWB2 + kb);
                ldsm_x4(bl, st + OFF_BL + boff + p * 16 * ROWB2 + kb);
                // pass-major schedule: accumulator reuse distance = 8 MMAs
#pragma unroll
                for (int q = 0; q < 2; q++)
#pragma unroll
                    for (int mt = 0; mt < 4; mt++)
                        mma16816(acc[mt][p * 2 + q], ah[mt], bh + q * 2);
#pragma unroll
                for (int q = 0; q < 2; q++)
#pragma unroll
                    for (int mt = 0; mt < 4; mt++)
                        mma16816(acc[mt][p * 2 + q], ah[mt], bl + q * 2);
#pragma unroll
                for (int q = 0; q < 2; q++)
#pragma unroll
                    for (int mt = 0; mt < 4; mt++)
                        mma16816(acc[mt][p * 2 + q], al[mt], bh + q * 2);
            }
        }
        __syncthreads();
    }

    // ---- fused epilogue: store g_h tile + per-row attention partial dots ---
    int r = lane >> 2, cq = lane & 3;
    int hh = ((bn + wn) >> 6) & 3;
    float2 as2[4], ad2[4];
#pragma unroll
    for (int nt = 0; nt < 4; nt++) {
        int col = bn + wn + nt * 8 + cq * 2;
        as2[nt] = *(const float2*)(asrc + col);
        ad2[nt] = *(const float2*)(adst + col);
    }
#pragma unroll
    for (int mt = 0; mt < 4; mt++) {
        int row0 = bm + wm + mt * 16 + r;
        float ps0 = 0.f, pd0 = 0.f, ps1 = 0.f, pd1 = 0.f;
#pragma unroll
        for (int nt = 0; nt < 4; nt++) {
            int col = bn + wn + nt * 8 + cq * 2;
            ps0 += acc[mt][nt][0] * as2[nt].x + acc[mt][nt][1] * as2[nt].y;
            pd0 += acc[mt][nt][0] * ad2[nt].x + acc[mt][nt][1] * ad2[nt].y;
            ps1 += acc[mt][nt][2] * as2[nt].x + acc[mt][nt][3] * as2[nt].y;
            pd1 += acc[mt][nt][2] * ad2[nt].x + acc[mt][nt][3] * ad2[nt].y;
            if (row0 < NNODES)
                *(float2*)(g_h + (size_t)row0 * WID + col) =
                    make_float2(acc[mt][nt][0], acc[mt][nt][1]);
            if (row0 + 8 < NNODES)
                *(float2*)(g_h + (size_t)(row0 + 8) * WID + col) =
                    make_float2(acc[mt][nt][2], acc[mt][nt][3]);
        }
        ps0 += __shfl_down_sync(0xffffffffu, ps0, 2);
        ps0 += __shfl_down_sync(0xffffffffu, ps0, 1);
        pd0 += __shfl_down_sync(0xffffffffu, pd0, 2);
        pd0 += __shfl_down_sync(0xffffffffu, pd0, 1);
        ps1 += __shfl_down_sync(0xffffffffu, ps1, 2);
        ps1 += __shfl_down_sync(0xffffffffu, ps1, 1);
        pd1 += __shfl_down_sync(0xffffffffu, pd1, 2);
        pd1 += __shfl_down_sync(0xffffffffu, pd1, 1);
        if (cq == 0) {
            if (row0 < NNODES) {
                atomicAdd(&g_als[row0 * 4 + hh], ps0);
                atomicAdd(&g_ald[row0 * 4 + hh], pd0);
            }
            if (row0 + 8 < NNODES) {
                atomicAdd(&g_als[(row0 + 8) * 4 + hh], ps1);
                atomicAdd(&g_ald[(row0 + 8) * 4 + hh], pd1);
            }
        }
    }
}

// --------- per-node softmax + aggregate + bias + ELU — 2 nodes per block ----
// warps 0-3: node base+0 (heads 0-3); warps 4-7: node base+1.
// phase 2: threads 0-127 -> node base+0 channels, 128-255 -> node base+1.
__global__ __launch_bounds__(256) void k_aggregate(const float* __restrict__ bias, int dosplit,
        const float* __restrict__ linw, const void* __restrict__ batch, float* out) {
    __shared__ int   sh_src[2][DCAP];
    __shared__ float sh_al[2][4][DCAP];
    __shared__ float s_inv[2][4];
    __shared__ float s_red[2][4];
    int tid = threadIdx.x, lane = tid & 31, w = tid >> 5;
    int half = tid >> 7;          // phase-2 / staging node side
    int ht = tid & 127;
    int wside = w >> 2;           // softmax node side for this warp
    int hw = w & 3;               // softmax head for this warp
    int base = blockIdx.x * 2;
    int rp0 = g_rowptr[base], rp1 = g_rowptr[base + 1], rp2 = g_rowptr[base + 2];
    int deg0 = rp1 - rp0, deg1 = rp2 - rp1;
    int startN = half ? rp1 : rp0;
    int degN   = half ? deg1 : deg0;
    int startW = wside ? rp1 : rp0;
    int degW   = wside ? deg1 : deg0;
    int nN = base + half, nW = base + wside;

    float v0, v1;
    int c = ht * 2;
    int hd = ht >> 5;             // head for phase-2 channels

    if (deg0 <= DCAP && deg1 <= DCAP) {
        // stage src + als rows into shared (each half stages its node)
        for (int i = ht; i < degN; i += 128) {
            int s = g_scsr[startN + i];
            sh_src[half][i] = s;
            float4 a = ((const float4*)g_als)[s];
            sh_al[half][0][i] = a.x; sh_al[half][1][i] = a.y;
            sh_al[half][2][i] = a.z; sh_al[half][3][i] = a.w;
        }
        __syncthreads();

        // per-head softmax (warp = one (node, head))
        float aldn = g_ald[nW * 4 + hw];
        float* alw = sh_al[wside][hw];
        float mx = -1e30f;
        for (int i = lane; i < degW; i += 32) {
            float v = alw[i] + aldn;
            v = v > 0.f ? v : 0.2f * v;
            alw[i] = v;
            mx = fmaxf(mx, v);
        }
#pragma unroll
        for (int o = 16; o; o >>= 1) mx = fmaxf(mx, __shfl_xor_sync(0xffffffffu, mx, o));
        float sum = 0.f;
        for (int i = lane; i < degW; i += 32) {
            float ex = expf(alw[i] - mx);
            alw[i] = ex;
            sum += ex;
        }
#pragma unroll
        for (int o = 16; o; o >>= 1) sum += __shfl_xor_sync(0xffffffffu, sum, o);
        if (lane == 0) s_inv[wside][hw] = 1.f / (sum + 1e-16f);
        __syncthreads();

        // aggregate with dual accumulators (2 independent gather chains)
        const float* alp = sh_al[half][hd];
        const int*   sp  = sh_src[half];
        float2 a0 = make_float2(0.f, 0.f), a1 = make_float2(0.f, 0.f);
        int i = 0;
#pragma unroll 2
        for (; i + 2 <= degN; i += 2) {
            float p = alp[i], q = alp[i + 1];
            float2 u = *((const float2*)(g_h + (size_t)sp[i] * WID) + ht);
            float2 v = *((const float2*)(g_h + (size_t)sp[i + 1] * WID) + ht);
            a0.x += p * u.x; a0.y += p * u.y;
            a1.x += q * v.x; a1.y += q * v.y;
        }
        if (i < degN) {
            float p = alp[i];
            float2 u = *((const float2*)(g_h + (size_t)sp[i] * WID) + ht);
            a0.x += p * u.x; a0.y += p * u.y;
        }
        float inv = s_inv[half][hd];
        v0 = (a0.x + a1.x) * inv + bias[c];
        v1 = (a0.y + a1.y) * inv + bias[c + 1];
    } else {
        // -------- fallback: either node deg > DCAP (block-uniform branch) ----
        float aldn = g_ald[nW * 4 + hw];
        float mx = -1e30f;
        for (int i = lane; i < degW; i += 32) {
            float v = g_als[g_scsr[startW + i] * 4 + hw] + aldn;
            v = v > 0.f ? v : 0.2f * v;
            g_esc[(size_t)(startW + i) * 4 + hw] = v;
            mx = fmaxf(mx, v);
        }
#pragma unroll
        for (int o = 16; o; o >>= 1) mx = fmaxf(mx, __shfl_xor_sync(0xffffffffu, mx, o));
        float sum = 0.f;
        for (int i = lane; i < degW; i += 32) {
            float ex = expf(g_esc[(size_t)(startW + i) * 4 + hw] - mx);
            g_esc[(size_t)(startW + i) * 4 + hw] = ex;
            sum += ex;
        }
#pragma unroll
        for (int o = 16; o; o >>= 1) sum += __shfl_xor_sync(0xffffffffu, sum, o);
        if (lane == 0) s_inv[wside][hw] = 1.f / (sum + 1e-16f);
        __syncthreads();

        float2 acc = make_float2(0.f, 0.f);
        for (int i = 0; i < degN; i++) {
            int s = g_scsr[startN + i];
            float a = g_esc[(size_t)(startN + i) * 4 + hd];
            float2 v = *((const float2*)(g_h + (size_t)s * WID) + ht);
            acc.x += a * v.x;
            acc.y += a * v.y;
        }
        float inv = s_inv[half][hd];
        v0 = acc.x * inv + bias[c];
        v1 = acc.y * inv + bias[c + 1];
    }

    v0 = v0 > 0.f ? v0 : expm1f(v0);           // ELU
    v1 = v1 > 0.f ? v1 : expm1f(v1);

    if (dosplit) {
        __nv_bfloat16 H0 = __float2bfloat16(v0), H1 = __float2bfloat16(v1);
        *((__nv_bfloat162*)(g_Ahi + (size_t)nN * WID + c)) = __nv_bfloat162(H0, H1);
        *((__nv_bfloat162*)(g_Alo + (size_t)nN * WID + c)) =
            __nv_bfloat162(__float2bfloat16(v0 - __bfloat162float(H0)),
                           __float2bfloat16(v1 - __bfloat162float(H1)));
    } else {
        // fused pooling + linear head (per node half)
        float part = v0 * linw[c] + v1 * linw[c + 1];
#pragma unroll
        for (int o = 16; o; o >>= 1) part += __shfl_xor_sync(0xffffffffu, part, o);
        if (lane == 0) s_red[half][w & 3] = part;
        __syncthreads();
        if (ht == 0) {
            float tot = (s_red[half][0] + s_red[half][1]) + (s_red[half][2] + s_red[half][3]);
            int g = g_i64flag ? (int)((const long long*)batch)[nN]
                              : ((const int*)batch)[nN];
            atomicAdd(&out[g], tot);
        }
    }
}

// ---------------- out init ----------------
__global__ void k_init_out(float* out, const float* __restrict__ lin_b) {
    int i = threadIdx.x;
    if (i < NG) out[i] = lin_b[0];
}

// ---------------- launch ----------------
extern "C" void kernel_launch(void* const* d_in, const int* in_sizes, int n_in,
                              void* d_out, int out_size) {
    const float* x     = (const float*)d_in[0];
    const void*  ei    = d_in[1];
    const void*  batch = d_in[3];
    const float* W[3]    = {(const float*)d_in[4],  (const float*)d_in[8],  (const float*)d_in[12]};
    const float* asrc[3] = {(const float*)d_in[5],  (const float*)d_in[9],  (const float*)d_in[13]};
    const float* adst[3] = {(const float*)d_in[6],  (const float*)d_in[10], (const float*)d_in[14]};
    const float* bb[3]   = {(const float*)d_in[7],  (const float*)d_in[11], (const float*)d_in[15]};
    const float* linw = (const float*)d_in[16];
    const float* linb = (const float*)d_in[17];
    float* out = (float*)d_out;

    static int smem_set = 0;
    if (!smem_set) {
        cudaFuncSetAttribute(k_gemm_mma, cudaFuncAttributeMaxDynamicSharedMemorySize, GSMEM2);
        smem_set = 1;
    }

    dim3 ggrid(MTILES, 2);
    int nodeGrid = (NNODES + 255) / 256;
    int aggGrid = NNODES / 2;   // 25000 (NNODES even)

    // probe + clear, layer-0 split (also zeroes g_als/ald), W0 split, GEMM0
    k_probe_clear<<<nodeGrid, 256>>>((const int*)ei);
    k_splitA<<<(NNODES * 128 / 4 + 255) / 256, 256>>>(x, NNODES * 128 / 4);
    k_splitW0<<<(128 * WID + 255) / 256, 256>>>(W[0], 128);
    k_gemm_mma<<<ggrid, 256, GSMEM2>>>(128, asrc[0], adst[0]);

    // CSR build (before first aggregate)
    k_count<<<(ETOT + 255) / 256, 256>>>(ei);
    int nb = (NNODES + 1023) / 1024;
    k_scan_blk<<<nb, 1024>>>();
    k_scan_top<<<1, 64>>>(nb);
    k_scan_fix<<<nodeGrid, 256>>>();
    k_fill<<<(ETOT + 255) / 256, 256>>>();

    // layer 0 tail
    k_aggregate<<<aggGrid, 256>>>(bb[0], 1, nullptr, nullptr, nullptr);

    // layer 1 (K=256); splitW also clears g_als/ald
    k_splitW<<<(256 * WID + 255) / 256, 256>>>(W[1], 256);
    k_gemm_mma<<<ggrid, 256, GSMEM2>>>(256, asrc[1], adst[1]);
    k_aggregate<<<aggGrid, 256>>>(bb[1], 1, nullptr, nullptr, nullptr);

    // layer 2 (K=256): aggregate fuses pooling + linear head
    k_splitW<<<(256 * WID + 255) / 256, 256>>>(W[2], 256);
    k_gemm_mma<<<ggrid, 256, GSMEM2>>>(256, asrc[2], adst[2]);
    k_init_out<<<1, 256>>>(out, linb);
    k_aggregate<<<aggGrid, 256>>>(bb[2], 0, linw, batch, out);
}

// round 12
// speedup vs baseline: 1.2616x; 1.2616x over previous
#include <cuda_runtime.h>
#include <cuda_bf16.h>
#include <math.h>
#include <stdint.h>

#define NNODES 50000
#define NEDG   400000
#define ETOT   450000
#define WID    256
#define NG     256
#define NPAD   50048        // 391 * 128
#define MTILES 391
#define DCAPW  64           // per-node degree cap for warp fast path

// ---------------- scratch globals ----------------
__device__ float g_h[(size_t)NNODES * WID];
__device__ float g_als[NNODES * 4];
__device__ float g_ald[NNODES * 4];
__device__ float g_esc[(size_t)ETOT * 4];    // fallback only (deg > DCAPW)
__device__ int   g_dst[ETOT];
__device__ int   g_srcE[ETOT];
__device__ int   g_scsr[ETOT];
__device__ int   g_deg[NNODES];
__device__ int   g_rowptr[NNODES + 1];
__device__ int   g_cursor[NNODES];
__device__ int   g_i64flag;
__device__ int   g_incl[NNODES];
__device__ int   g_bsum[64];
__device__ int   g_boff[64];
// bf16 split operands (zero-init covers M padding)
__device__ __align__(16) __nv_bfloat16 g_Ahi[(size_t)NPAD * WID];
__device__ __align__(16) __nv_bfloat16 g_Alo[(size_t)NPAD * WID];
__device__ __align__(16) __nv_bfloat16 g_Bhi[WID * WID];   // [N=256][K]
__device__ __align__(16) __nv_bfloat16 g_Blo[WID * WID];

// ---------------- helpers ----------------
__device__ __forceinline__ uint32_t smem_u32(const void* p) {
    uint32_t a;
    asm("{ .reg .u64 t; cvta.to.shared.u64 t, %1; cvt.u32.u64 %0, t; }" : "=r"(a) : "l"(p));
    return a;
}
__device__ __forceinline__ void cp16(uint32_t s, const void* g) {
    asm volatile("cp.async.cg.shared.global [%0], [%1], 16;" :: "r"(s), "l"(g));
}
#define CP_COMMIT()  asm volatile("cp.async.commit_group;" ::: "memory")
#define CP_WAIT(n)   asm volatile("cp.async.wait_group %0;" :: "n"(n) : "memory")

__device__ __forceinline__ void mma16816(float* d, const uint32_t* a, const uint32_t* b) {
    asm volatile(
        "mma.sync.aligned.m16n8k16.row.col.f32.bf16.bf16.f32 "
        "{%0,%1,%2,%3}, {%4,%5,%6,%7}, {%8,%9}, {%0,%1,%2,%3};"
        : "+f"(d[0]), "+f"(d[1]), "+f"(d[2]), "+f"(d[3])
        : "r"(a[0]), "r"(a[1]), "r"(a[2]), "r"(a[3]), "r"(b[0]), "r"(b[1]));
}
__device__ __forceinline__ void ldsm_x4(uint32_t* r, uint32_t addr) {
    asm volatile("ldmatrix.sync.aligned.m8n8.x4.shared.b16 {%0,%1,%2,%3}, [%4];"
        : "=r"(r[0]), "=r"(r[1]), "=r"(r[2]), "=r"(r[3]) : "r"(addr));
}

// ---------------- dtype probe + clear deg ----------------
__global__ void k_probe_clear(const int* __restrict__ ei32) {
    int i = blockIdx.x * blockDim.x + threadIdx.x;
    if (i < NNODES) g_deg[i] = 0;
    if (i == 0) {
        int allzero = 1;
#pragma unroll
        for (int j = 0; j < 8; j++) allzero &= (ei32[2 * j + 1] == 0);
        g_i64flag = allzero;
    }
}

// ---------------- CSR build ----------------
__global__ void k_count(const void* __restrict__ ei) {
    int i = blockIdx.x * blockDim.x + threadIdx.x;
    if (i >= ETOT) return;
    int s, d;
    if (i < NEDG) {
        if (g_i64flag) {
            const long long* p = (const long long*)ei;
            s = (int)p[i]; d = (int)p[NEDG + i];
        } else {
            const int* p = (const int*)ei;
            s = p[i]; d = p[NEDG + i];
        }
    } else {
        s = i - NEDG; d = s;
    }
    g_srcE[i] = s;
    g_dst[i] = d;
    atomicAdd(&g_deg[d], 1);
}

__global__ __launch_bounds__(1024) void k_scan_blk() {
    __shared__ int wsum[32];
    int tid = threadIdx.x, lane = tid & 31, w = tid >> 5;
    int i = blockIdx.x * 1024 + tid;
    int v = (i < NNODES) ? g_deg[i] : 0;
    int x = v;
#pragma unroll
    for (int o = 1; o < 32; o <<= 1) {
        int t = __shfl_up_sync(0xffffffffu, x, o);
        if (lane >= o) x += t;
    }
    if (lane == 31) wsum[w] = x;
    __syncthreads();
    if (w == 0) {
        int s = wsum[lane];
#pragma unroll
        for (int o = 1; o < 32; o <<= 1) {
            int t = __shfl_up_sync(0xffffffffu, s, o);
            if (lane >= o) s += t;
        }
        wsum[lane] = s;
    }
    __syncthreads();
    int incl = x + (w ? wsum[w - 1] : 0);
    if (i < NNODES) g_incl[i] = incl;
    if (tid == 1023) g_bsum[blockIdx.x] = incl;
}

// 64-thread shfl scan over block sums (exclusive)
__global__ void k_scan_top(int nb) {
    __shared__ int ws[2];
    int tid = threadIdx.x, lane = tid & 31, wi = tid >> 5;
    int v = (tid < nb) ? g_bsum[tid] : 0;
    int x = v;
#pragma unroll
    for (int o = 1; o < 32; o <<= 1) {
        int t = __shfl_up_sync(0xffffffffu, x, o);
        if (lane >= o) x += t;
    }
    if (lane == 31) ws[wi] = x;
    __syncthreads();
    int incl = x + ((wi == 1) ? ws[0] : 0);
    if (tid < nb) g_boff[tid] = incl - v;
}

__global__ void k_scan_fix() {
    int i = blockIdx.x * blockDim.x + threadIdx.x;
    if (i >= NNODES) return;
    int incl = g_incl[i] + g_boff[i >> 10];
    g_rowptr[i + 1] = incl;
    g_cursor[i] = incl - g_deg[i];
    if (i == 0) g_rowptr[0] = 0;
}

__global__ void k_fill() {
    int i = blockIdx.x * blockDim.x + threadIdx.x;
    if (i >= ETOT) return;
    int p = atomicAdd(&g_cursor[g_dst[i]], 1);
    g_scsr[p] = g_srcE[i];
}

// ---------------- fp32 -> bf16 hi/lo (layer 0; also zeroes g_als/ald) -------
__global__ void k_splitA(const float* __restrict__ in, int n4) {
    int i = blockIdx.x * blockDim.x + threadIdx.x;
    if (i < NNODES) {
        float4 z = make_float4(0.f, 0.f, 0.f, 0.f);
        ((float4*)g_als)[i] = z;
        ((float4*)g_ald)[i] = z;
    }
    if (i >= n4) return;
    float4 v = *(const float4*)(in + (size_t)i * 4);
    __nv_bfloat16 hx = __float2bfloat16(v.x), hy = __float2bfloat16(v.y);
    __nv_bfloat16 hz = __float2bfloat16(v.z), hw = __float2bfloat16(v.w);
    __nv_bfloat16 lx = __float2bfloat16(v.x - __bfloat162float(hx));
    __nv_bfloat16 ly = __float2bfloat16(v.y - __bfloat162float(hy));
    __nv_bfloat16 lz = __float2bfloat16(v.z - __bfloat162float(hz));
    __nv_bfloat16 lw = __float2bfloat16(v.w - __bfloat162float(hw));
    __nv_bfloat162* ph = (__nv_bfloat162*)g_Ahi + (size_t)i * 2;
    __nv_bfloat162* pl = (__nv_bfloat162*)g_Alo + (size_t)i * 2;
    ph[0] = __nv_bfloat162(hx, hy); ph[1] = __nv_bfloat162(hz, hw);
    pl[0] = __nv_bfloat162(lx, ly); pl[1] = __nv_bfloat162(lz, lw);
}

// W split for layers 1/2 — also clears g_als/g_ald; layer 2 also inits out
__global__ void k_splitW(const float* __restrict__ W, int K,
                         float* out, const float* __restrict__ linb) {
    int i = blockIdx.x * blockDim.x + threadIdx.x;
    if (i < NNODES) {
        float4 z = make_float4(0.f, 0.f, 0.f, 0.f);
        ((float4*)g_als)[i] = z;
        ((float4*)g_ald)[i] = z;
    }
    if (out && i < NG) out[i] = linb[0];
    if (i >= K * WID) return;
    int k = i >> 8, n = i & 255;
    float v = W[i];
    __nv_bfloat16 h = __float2bfloat16(v);
    __nv_bfloat16 l = __float2bfloat16(v - __bfloat162float(h));
    g_Bhi[n * K + k] = h;
    g_Blo[n * K + k] = l;
}

// W split for layer 0 (no clear — splitA does it)
__global__ void k_splitW0(const float* __restrict__ W, int K) {
    int i = blockIdx.x * blockDim.x + threadIdx.x;
    if (i >= K * WID) return;
    int k = i >> 8, n = i & 255;
    float v = W[i];
    __nv_bfloat16 h = __float2bfloat16(v);
    __nv_bfloat16 l = __float2bfloat16(v - __bfloat162float(h));
    g_Bhi[n * K + k] = h;
    g_Blo[n * K + k] = l;
}

// ---------------- HMMA GEMM + fused attention epilogue ----------------
#define ROWB2  80
#define OFF_AH 0
#define OFF_AL 10240
#define OFF_BH 20480
#define OFF_BL 30720
#define STG2   40960
#define GSMEM2 81920

__device__ __forceinline__ void load_stage2(uint32_t sb, int bm, int bn, int K,
                                            int k0, int tid) {
#pragma unroll
    for (int i = 0; i < 2; i++) {
        int idx = tid + i * 256;
        int row = idx >> 2, seg = idx & 3;
        uint32_t so = row * ROWB2 + seg * 16;
        size_t ga = (size_t)(bm + row) * K + k0 + seg * 8;
        size_t gb = (size_t)(bn + row) * K + k0 + seg * 8;
        cp16(sb + OFF_AH + so, g_Ahi + ga);
        cp16(sb + OFF_AL + so, g_Alo + ga);
        cp16(sb + OFF_BH + so, g_Bhi + gb);
        cp16(sb + OFF_BL + so, g_Blo + gb);
    }
}

__global__ __launch_bounds__(256, 2) void k_gemm_mma(int K,
        const float* __restrict__ asrc, const float* __restrict__ adst) {
    extern __shared__ char smem[];
    uint32_t sb = smem_u32(smem);
    int tid = threadIdx.x, lane = tid & 31, w = tid >> 5;
    int bm = blockIdx.x * 128, bn = blockIdx.y * 128;
    int wm = (w >> 2) * 64, wn = (w & 3) * 32;

    float acc[4][4][4];
#pragma unroll
    for (int mt = 0; mt < 4; mt++)
#pragma unroll
        for (int nt = 0; nt < 4; nt++)
#pragma unroll
            for (int j = 0; j < 4; j++) acc[mt][nt][j] = 0.f;

    uint32_t aoff = (uint32_t)(wm + (lane & 15)) * ROWB2 + (lane >> 4) * 16;
    uint32_t boff = (uint32_t)(wn + ((lane >> 4) & 1) * 8 + (lane & 7)) * ROWB2
                  + ((lane >> 3) & 1) * 16;

    const int nc = K >> 5;
    load_stage2(sb, bm, bn, K, 0, tid);
    CP_COMMIT();

    for (int kc = 0; kc < nc; kc++) {
        if (kc + 1 < nc) {
            load_stage2(sb + ((kc + 1) & 1) * STG2, bm, bn, K, (kc + 1) << 5, tid);
            CP_COMMIT();
            CP_WAIT(1);
        } else {
            CP_WAIT(0);
        }
        __syncthreads();
        uint32_t st = sb + (kc & 1) * STG2;
#pragma unroll
        for (int ks = 0; ks < 2; ks++) {
            uint32_t kb = ks * 32;
            uint32_t ah[4][4], al[4][4];
#pragma unroll
            for (int mt = 0; mt < 4; mt++) {
                ldsm_x4(ah[mt], st + OFF_AH + aoff + mt * 16 * ROWB2 + kb);
                ldsm_x4(al[mt], st + OFF_AL + aoff + mt * 16 * ROWB2 + kb);
            }
#pragma unroll
            for (int p = 0; p < 2; p++) {
                uint32_t bh[4], bl[4];
                ldsm_x4(bh, st + OFF_BH + boff + p * 16 * ROWB2 + kb);
                ldsm_x4(bl, st + OFF_BL + boff + p * 16 * ROWB2 + kb);
                // pass-major schedule: accumulator reuse distance = 8 MMAs
#pragma unroll
                for (int q = 0; q < 2; q++)
#pragma unroll
                    for (int mt = 0; mt < 4; mt++)
                        mma16816(acc[mt][p * 2 + q], ah[mt], bh + q * 2);
#pragma unroll
                for (int q = 0; q < 2; q++)
#pragma unroll
                    for (int mt = 0; mt < 4; mt++)
                        mma16816(acc[mt][p * 2 + q], ah[mt], bl + q * 2);
#pragma unroll
                for (int q = 0; q < 2; q++)
#pragma unroll
                    for (int mt = 0; mt < 4; mt++)
                        mma16816(acc[mt][p * 2 + q], al[mt], bh + q * 2);
            }
        }
        __syncthreads();
    }

    // ---- fused epilogue: store g_h tile + per-row attention partial dots ---
    int r = lane >> 2, cq = lane & 3;
    int hh = ((bn + wn) >> 6) & 3;
    float2 as2[4], ad2[4];
#pragma unroll
    for (int nt = 0; nt < 4; nt++) {
        int col = bn + wn + nt * 8 + cq * 2;
        as2[nt] = *(const float2*)(asrc + col);
        ad2[nt] = *(const float2*)(adst + col);
    }
#pragma unroll
    for (int mt = 0; mt < 4; mt++) {
        int row0 = bm + wm + mt * 16 + r;
        float ps0 = 0.f, pd0 = 0.f, ps1 = 0.f, pd1 = 0.f;
#pragma unroll
        for (int nt = 0; nt < 4; nt++) {
            int col = bn + wn + nt * 8 + cq * 2;
            ps0 += acc[mt][nt][0] * as2[nt].x + acc[mt][nt][1] * as2[nt].y;
            pd0 += acc[mt][nt][0] * ad2[nt].x + acc[mt][nt][1] * ad2[nt].y;
            ps1 += acc[mt][nt][2] * as2[nt].x + acc[mt][nt][3] * as2[nt].y;
            pd1 += acc[mt][nt][2] * ad2[nt].x + acc[mt][nt][3] * ad2[nt].y;
            if (row0 < NNODES)
                *(float2*)(g_h + (size_t)row0 * WID + col) =
                    make_float2(acc[mt][nt][0], acc[mt][nt][1]);
            if (row0 + 8 < NNODES)
                *(float2*)(g_h + (size_t)(row0 + 8) * WID + col) =
                    make_float2(acc[mt][nt][2], acc[mt][nt][3]);
        }
        ps0 += __shfl_down_sync(0xffffffffu, ps0, 2);
        ps0 += __shfl_down_sync(0xffffffffu, ps0, 1);
        pd0 += __shfl_down_sync(0xffffffffu, pd0, 2);
        pd0 += __shfl_down_sync(0xffffffffu, pd0, 1);
        ps1 += __shfl_down_sync(0xffffffffu, ps1, 2);
        ps1 += __shfl_down_sync(0xffffffffu, ps1, 1);
        pd1 += __shfl_down_sync(0xffffffffu, pd1, 2);
        pd1 += __shfl_down_sync(0xffffffffu, pd1, 1);
        if (cq == 0) {
            if (row0 < NNODES) {
                atomicAdd(&g_als[row0 * 4 + hh], ps0);
                atomicAdd(&g_ald[row0 * 4 + hh], pd0);
            }
            if (row0 + 8 < NNODES) {
                atomicAdd(&g_als[(row0 + 8) * 4 + hh], ps1);
                atomicAdd(&g_ald[(row0 + 8) * 4 + hh], pd1);
            }
        }
    }
}

// --------- aggregation: WARP per node — no block syncs ---------
// lane owns channels lane*8..lane*8+7; head = lane>>3 (8-lane groups).
__global__ __launch_bounds__(128) void k_aggregate(const float* __restrict__ bias, int dosplit,
        const float* __restrict__ linw, const void* __restrict__ batch, float* out) {
    __shared__ float s_al[4][4][DCAPW];   // [warp][head][edge]
    __shared__ int   s_src[4][DCAPW];
    int wid = threadIdx.x >> 5, lane = threadIdx.x & 31;
    int n = blockIdx.x * 4 + wid;
    int start = g_rowptr[n];
    int deg = g_rowptr[n + 1] - start;
    int g = lane >> 3;          // head for this lane's channels & softmax group
    int j = lane & 7;

    float4 aldn = ((const float4*)g_ald)[n];   // broadcast load
    float inv;
    float acc[8];
#pragma unroll
    for (int k = 0; k < 8; k++) acc[k] = 0.f;
    int c = lane * 8;

    if (deg <= DCAPW) {
        // stage src + leaky(als+ald) into warp-private shared
        for (int i = lane; i < deg; i += 32) {
            int s = g_scsr[start + i];
            s_src[wid][i] = s;
            float4 a = ((const float4*)g_als)[s];
            float t0 = a.x + aldn.x; t0 = t0 > 0.f ? t0 : 0.2f * t0;
            float t1 = a.y + aldn.y; t1 = t1 > 0.f ? t1 : 0.2f * t1;
            float t2 = a.z + aldn.z; t2 = t2 > 0.f ? t2 : 0.2f * t2;
            float t3 = a.w + aldn.w; t3 = t3 > 0.f ? t3 : 0.2f * t3;
            s_al[wid][0][i] = t0; s_al[wid][1][i] = t1;
            s_al[wid][2][i] = t2; s_al[wid][3][i] = t3;
        }
        __syncwarp();

        // softmax per head within 8-lane group
        float mx = -1e30f;
        for (int i = j; i < deg; i += 8) mx = fmaxf(mx, s_al[wid][g][i]);
#pragma unroll
        for (int o = 4; o; o >>= 1) mx = fmaxf(mx, __shfl_xor_sync(0xffffffffu, mx, o));
        float sum = 0.f;
        for (int i = j; i < deg; i += 8) {
            float ex = expf(s_al[wid][g][i] - mx);
            s_al[wid][g][i] = ex;
            sum += ex;
        }
#pragma unroll
        for (int o = 4; o; o >>= 1) sum += __shfl_xor_sync(0xffffffffu, sum, o);
        inv = 1.f / (sum + 1e-16f);
        __syncwarp();

        // gather: dual accumulator chains
        const float* alp = s_al[wid][g];
        const int*   sp  = s_src[wid];
        float b[8];
#pragma unroll
        for (int k = 0; k < 8; k++) b[k] = 0.f;
        int i = 0;
        for (; i + 2 <= deg; i += 2) {
            float p = alp[i], q = alp[i + 1];
            const float* r0 = g_h + (size_t)sp[i] * WID + c;
            const float* r1 = g_h + (size_t)sp[i + 1] * WID + c;
            float4 u0 = *(const float4*)r0, u1 = *(const float4*)(r0 + 4);
            float4 w0 = *(const float4*)r1, w1 = *(const float4*)(r1 + 4);
            acc[0] += p * u0.x; acc[1] += p * u0.y; acc[2] += p * u0.z; acc[3] += p * u0.w;
            acc[4] += p * u1.x; acc[5] += p * u1.y; acc[6] += p * u1.z; acc[7] += p * u1.w;
            b[0] += q * w0.x; b[1] += q * w0.y; b[2] += q * w0.z; b[3] += q * w0.w;
            b[4] += q * w1.x; b[5] += q * w1.y; b[6] += q * w1.z; b[7] += q * w1.w;
        }
        if (i < deg) {
            float p = alp[i];
            const float* r0 = g_h + (size_t)sp[i] * WID + c;
            float4 u0 = *(const float4*)r0, u1 = *(const float4*)(r0 + 4);
            acc[0] += p * u0.x; acc[1] += p * u0.y; acc[2] += p * u0.z; acc[3] += p * u0.w;
            acc[4] += p * u1.x; acc[5] += p * u1.y; acc[6] += p * u1.z; acc[7] += p * u1.w;
        }
#pragma unroll
        for (int k = 0; k < 8; k++) acc[k] += b[k];
    } else {
        // -------- fallback: deg > DCAPW, warp-local via g_esc ----------
        float4 mx4 = make_float4(-1e30f, -1e30f, -1e30f, -1e30f);
        for (int i = lane; i < deg; i += 32) {
            float4 a = ((const float4*)g_als)[g_scsr[start + i]];
            a.x += aldn.x; a.x = a.x > 0.f ? a.x : 0.2f * a.x;
            a.y += aldn.y; a.y = a.y > 0.f ? a.y : 0.2f * a.y;
            a.z += aldn.z; a.z = a.z > 0.f ? a.z : 0.2f * a.z;
            a.w += aldn.w; a.w = a.w > 0.f ? a.w : 0.2f * a.w;
            ((float4*)g_esc)[start + i] = a;
            mx4.x = fmaxf(mx4.x, a.x); mx4.y = fmaxf(mx4.y, a.y);
            mx4.z = fmaxf(mx4.z, a.z); mx4.w = fmaxf(mx4.w, a.w);
        }
#pragma unroll
        for (int o = 16; o; o >>= 1) {
            mx4.x = fmaxf(mx4.x, __shfl_xor_sync(0xffffffffu, mx4.x, o));
            mx4.y = fmaxf(mx4.y, __shfl_xor_sync(0xffffffffu, mx4.y, o));
            mx4.z = fmaxf(mx4.z, __shfl_xor_sync(0xffffffffu, mx4.z, o));
            mx4.w = fmaxf(mx4.w, __shfl_xor_sync(0xffffffffu, mx4.w, o));
        }
        __threadfence_block();
        __syncwarp();
        float4 sum4 = make_float4(0.f, 0.f, 0.f, 0.f);
        for (int i = lane; i < deg; i += 32) {
            float4 e = ((float4*)g_esc)[start + i];
            e.x = expf(e.x - mx4.x); e.y = expf(e.y - mx4.y);
            e.z = expf(e.z - mx4.z); e.w = expf(e.w - mx4.w);
            ((float4*)g_esc)[start + i] = e;
            sum4.x += e.x; sum4.y += e.y; sum4.z += e.z; sum4.w += e.w;
        }
#pragma unroll
        for (int o = 16; o; o >>= 1) {
            sum4.x += __shfl_xor_sync(0xffffffffu, sum4.x, o);
            sum4.y += __shfl_xor_sync(0xffffffffu, sum4.y, o);
            sum4.z += __shfl_xor_sync(0xffffffffu, sum4.z, o);
            sum4.w += __shfl_xor_sync(0xffffffffu, sum4.w, o);
        }
        float sums[4] = {sum4.x, sum4.y, sum4.z, sum4.w};
        inv = 1.f / (sums[g] + 1e-16f);
        __threadfence_block();
        __syncwarp();
        for (int i = 0; i < deg; i++) {
            float a = g_esc[(size_t)(start + i) * 4 + g];
            const float* r0 = g_h + (size_t)g_scsr[start + i] * WID + c;
            float4 u0 = *(const float4*)r0, u1 = *(const float4*)(r0 + 4);
            acc[0] += a * u0.x; acc[1] += a * u0.y; acc[2] += a * u0.z; acc[3] += a * u0.w;
            acc[4] += a * u1.x; acc[5] += a * u1.y; acc[6] += a * u1.z; acc[7] += a * u1.w;
        }
    }

    // ---- epilogue: bias + ELU, then split or pool ----
    float4 b0 = *(const float4*)(bias + c), b1 = *(const float4*)(bias + c + 4);
    float v[8];
    v[0] = acc[0] * inv + b0.x; v[1] = acc[1] * inv + b0.y;
    v[2] = acc[2] * inv + b0.z; v[3] = acc[3] * inv + b0.w;
    v[4] = acc[4] * inv + b1.x; v[5] = acc[5] * inv + b1.y;
    v[6] = acc[6] * inv + b1.z; v[7] = acc[7] * inv + b1.w;
#pragma unroll
    for (int k = 0; k < 8; k++) v[k] = v[k] > 0.f ? v[k] : expm1f(v[k]);

    if (dosplit) {
        __align__(16) __nv_bfloat162 H[4], L[4];
#pragma unroll
        for (int k = 0; k < 4; k++) {
            __nv_bfloat16 h0 = __float2bfloat16(v[2 * k]);
            __nv_bfloat16 h1 = __float2bfloat16(v[2 * k + 1]);
            H[k] = __nv_bfloat162(h0, h1);
            L[k] = __nv_bfloat162(__float2bfloat16(v[2 * k] - __bfloat162float(h0)),
                                  __float2bfloat16(v[2 * k + 1] - __bfloat162float(h1)));
        }
        *(uint4*)(g_Ahi + (size_t)n * WID + c) = *(uint4*)H;
        *(uint4*)(g_Alo + (size_t)n * WID + c) = *(uint4*)L;
    } else {
        float4 w0 = *(const float4*)(linw + c), w1 = *(const float4*)(linw + c + 4);
        float part = v[0] * w0.x + v[1] * w0.y + v[2] * w0.z + v[3] * w0.w
                   + v[4] * w1.x + v[5] * w1.y + v[6] * w1.z + v[7] * w1.w;
#pragma unroll
        for (int o = 16; o; o >>= 1) part += __shfl_xor_sync(0xffffffffu, part, o);
        if (lane == 0) {
            int gg = g_i64flag ? (int)((const long long*)batch)[n]
                               : ((const int*)batch)[n];
            atomicAdd(&out[gg], part);
        }
    }
}

// ---------------- launch ----------------
extern "C" void kernel_launch(void* const* d_in, const int* in_sizes, int n_in,
                              void* d_out, int out_size) {
    const float* x     = (const float*)d_in[0];
    const void*  ei    = d_in[1];
    const void*  batch = d_in[3];
    const float* W[3]    = {(const float*)d_in[4],  (const float*)d_in[8],  (const float*)d_in[12]};
    const float* asrc[3] = {(const float*)d_in[5],  (const float*)d_in[9],  (const float*)d_in[13]};
    const float* adst[3] = {(const float*)d_in[6],  (const float*)d_in[10], (const float*)d_in[14]};
    const float* bb[3]   = {(const float*)d_in[7],  (const float*)d_in[11], (const float*)d_in[15]};
    const float* linw = (const float*)d_in[16];
    const float* linb = (const float*)d_in[17];
    float* out = (float*)d_out;

    static int smem_set = 0;
    if (!smem_set) {
        cudaFuncSetAttribute(k_gemm_mma, cudaFuncAttributeMaxDynamicSharedMemorySize, GSMEM2);
        smem_set = 1;
    }

    dim3 ggrid(MTILES, 2);
    int nodeGrid = (NNODES + 255) / 256;
    int aggGrid = NNODES / 4;   // 12500 (NNODES divisible by 4)

    // probe + clear, layer-0 split (also zeroes g_als/ald), W0 split, GEMM0
    k_probe_clear<<<nodeGrid, 256>>>((const int*)ei);
    k_splitA<<<(NNODES * 128 / 4 + 255) / 256, 256>>>(x, NNODES * 128 / 4);
    k_splitW0<<<(128 * WID + 255) / 256, 256>>>(W[0], 128);
    k_gemm_mma<<<ggrid, 256, GSMEM2>>>(128, asrc[0], adst[0]);

    // CSR build (before first aggregate)
    k_count<<<(ETOT + 255) / 256, 256>>>(ei);
    int nb = (NNODES + 1023) / 1024;
    k_scan_blk<<<nb, 1024>>>();
    k_scan_top<<<1, 64>>>(nb);
    k_scan_fix<<<nodeGrid, 256>>>();
    k_fill<<<(ETOT + 255) / 256, 256>>>();

    // layer 0 tail
    k_aggregate<<<aggGrid, 128>>>(bb[0], 1, nullptr, nullptr, nullptr);

    // layer 1 (K=256); splitW also clears g_als/ald
    k_splitW<<<(256 * WID + 255) / 256, 256>>>(W[1], 256, nullptr, nullptr);
    k_gemm_mma<<<ggrid, 256, GSMEM2>>>(256, asrc[1], adst[1]);
    k_aggregate<<<aggGrid, 128>>>(bb[1], 1, nullptr, nullptr, nullptr);

    // layer 2 (K=256): splitW also inits out; aggregate fuses pooling + head
    k_splitW<<<(256 * WID + 255) / 256, 256>>>(W[2], 256, out, linb);
    k_gemm_mma<<<ggrid, 256, GSMEM2>>>(256, asrc[2], adst[2]);
    k_aggregate<<<aggGrid, 128>>>(bb[2], 0, linw, batch, out);
}

// round 13
// speedup vs baseline: 1.3862x; 1.0987x over previous
#include <cuda_runtime.h>
#include <math.h>
#include <stdint.h>

#define NNODES 50000
#define NEDG   400000
#define ETOT   450000
#define WID    256
#define NG     256
#define NPAD   50048        // 391 * 128
#define MTILES 391
#define DCAPW  64           // per-node degree cap for warp fast path

// ---------------- scratch globals ----------------
__device__ float g_h[(size_t)NNODES * WID];
__device__ float g_als[NNODES * 4];
__device__ float g_ald[NNODES * 4];
__device__ float g_esc[(size_t)ETOT * 4];    // fallback only (deg > DCAPW)
__device__ int   g_dst[ETOT];
__device__ int   g_srcE[ETOT];
__device__ int   g_scsr[ETOT];
__device__ int   g_deg[NNODES];
__device__ int   g_rowptr[NNODES + 1];
__device__ int   g_cursor[NNODES];
__device__ int   g_i64flag;
__device__ int   g_incl[NNODES];
__device__ int   g_bsum[64];
__device__ int   g_boff[64];
// tf32-rounded operands (zero-init covers M padding)
__device__ __align__(16) float g_Af[(size_t)NPAD * WID];
__device__ __align__(16) float g_Bf[WID * WID];   // [N=256][K]

// ---------------- helpers ----------------
__device__ __forceinline__ uint32_t smem_u32(const void* p) {
    uint32_t a;
    asm("{ .reg .u64 t; cvta.to.shared.u64 t, %1; cvt.u32.u64 %0, t; }" : "=r"(a) : "l"(p));
    return a;
}
__device__ __forceinline__ void cp16(uint32_t s, const void* g) {
    asm volatile("cp.async.cg.shared.global [%0], [%1], 16;" :: "r"(s), "l"(g));
}
#define CP_COMMIT()  asm volatile("cp.async.commit_group;" ::: "memory")
#define CP_WAIT(n)   asm volatile("cp.async.wait_group %0;" :: "n"(n) : "memory")

__device__ __forceinline__ float to_tf32(float x) {
    uint32_t r;
    asm("cvt.rna.tf32.f32 %0, %1;" : "=r"(r) : "f"(x));
    return __uint_as_float(r);
}
__device__ __forceinline__ void mma_tf32(float* d, const uint32_t* a, const uint32_t* b) {
    asm volatile(
        "mma.sync.aligned.m16n8k8.row.col.f32.tf32.tf32.f32 "
        "{%0,%1,%2,%3}, {%4,%5,%6,%7}, {%8,%9}, {%0,%1,%2,%3};"
        : "+f"(d[0]), "+f"(d[1]), "+f"(d[2]), "+f"(d[3])
        : "r"(a[0]), "r"(a[1]), "r"(a[2]), "r"(a[3]), "r"(b[0]), "r"(b[1]));
}

// ---------------- dtype probe + clear deg ----------------
__global__ void k_probe_clear(const int* __restrict__ ei32) {
    int i = blockIdx.x * blockDim.x + threadIdx.x;
    if (i < NNODES) g_deg[i] = 0;
    if (i == 0) {
        int allzero = 1;
#pragma unroll
        for (int j = 0; j < 8; j++) allzero &= (ei32[2 * j + 1] == 0);
        g_i64flag = allzero;
    }
}

// ---------------- CSR build ----------------
__global__ void k_count(const void* __restrict__ ei) {
    int i = blockIdx.x * blockDim.x + threadIdx.x;
    if (i >= ETOT) return;
    int s, d;
    if (i < NEDG) {
        if (g_i64flag) {
            const long long* p = (const long long*)ei;
            s = (int)p[i]; d = (int)p[NEDG + i];
        } else {
            const int* p = (const int*)ei;
            s = p[i]; d = p[NEDG + i];
        }
    } else {
        s = i - NEDG; d = s;
    }
    g_srcE[i] = s;
    g_dst[i] = d;
    atomicAdd(&g_deg[d], 1);
}

__global__ __launch_bounds__(1024) void k_scan_blk() {
    __shared__ int wsum[32];
    int tid = threadIdx.x, lane = tid & 31, w = tid >> 5;
    int i = blockIdx.x * 1024 + tid;
    int v = (i < NNODES) ? g_deg[i] : 0;
    int x = v;
#pragma unroll
    for (int o = 1; o < 32; o <<= 1) {
        int t = __shfl_up_sync(0xffffffffu, x, o);
        if (lane >= o) x += t;
    }
    if (lane == 31) wsum[w] = x;
    __syncthreads();
    if (w == 0) {
        int s = wsum[lane];
#pragma unroll
        for (int o = 1; o < 32; o <<= 1) {
            int t = __shfl_up_sync(0xffffffffu, s, o);
            if (lane >= o) s += t;
        }
        wsum[lane] = s;
    }
    __syncthreads();
    int incl = x + (w ? wsum[w - 1] : 0);
    if (i < NNODES) g_incl[i] = incl;
    if (tid == 1023) g_bsum[blockIdx.x] = incl;
}

__global__ void k_scan_top(int nb) {
    __shared__ int ws[2];
    int tid = threadIdx.x, lane = tid & 31, wi = tid >> 5;
    int v = (tid < nb) ? g_bsum[tid] : 0;
    int x = v;
#pragma unroll
    for (int o = 1; o < 32; o <<= 1) {
        int t = __shfl_up_sync(0xffffffffu, x, o);
        if (lane >= o) x += t;
    }
    if (lane == 31) ws[wi] = x;
    __syncthreads();
    int incl = x + ((wi == 1) ? ws[0] : 0);
    if (tid < nb) g_boff[tid] = incl - v;
}

__global__ void k_scan_fix() {
    int i = blockIdx.x * blockDim.x + threadIdx.x;
    if (i >= NNODES) return;
    int incl = g_incl[i] + g_boff[i >> 10];
    g_rowptr[i + 1] = incl;
    g_cursor[i] = incl - g_deg[i];
    if (i == 0) g_rowptr[0] = 0;
}

__global__ void k_fill() {
    int i = blockIdx.x * blockDim.x + threadIdx.x;
    if (i >= ETOT) return;
    int p = atomicAdd(&g_cursor[g_dst[i]], 1);
    g_scsr[p] = g_srcE[i];
}

// ---------------- fp32 -> tf32 round (layer 0; also zeroes g_als/ald) -------
__global__ void k_splitA(const float* __restrict__ in, int n4) {
    int i = blockIdx.x * blockDim.x + threadIdx.x;
    if (i < NNODES) {
        float4 z = make_float4(0.f, 0.f, 0.f, 0.f);
        ((float4*)g_als)[i] = z;
        ((float4*)g_ald)[i] = z;
    }
    if (i >= n4) return;
    float4 v = *(const float4*)(in + (size_t)i * 4);
    v.x = to_tf32(v.x); v.y = to_tf32(v.y);
    v.z = to_tf32(v.z); v.w = to_tf32(v.w);
    ((float4*)g_Af)[i] = v;
}

// W split for layers 1/2 — also clears g_als/g_ald; layer 2 also inits out
__global__ void k_splitW(const float* __restrict__ W, int K,
                         float* out, const float* __restrict__ linb) {
    int i = blockIdx.x * blockDim.x + threadIdx.x;
    if (i < NNODES) {
        float4 z = make_float4(0.f, 0.f, 0.f, 0.f);
        ((float4*)g_als)[i] = z;
        ((float4*)g_ald)[i] = z;
    }
    if (out && i < NG) out[i] = linb[0];
    if (i >= K * WID) return;
    int k = i >> 8, n = i & 255;
    g_Bf[n * K + k] = to_tf32(W[i]);
}

// W split for layer 0 (no clear — splitA does it)
__global__ void k_splitW0(const float* __restrict__ W, int K) {
    int i = blockIdx.x * blockDim.x + threadIdx.x;
    if (i >= K * WID) return;
    int k = i >> 8, n = i & 255;
    g_Bf[n * K + k] = to_tf32(W[i]);
}

// ---------------- tf32 HMMA GEMM + fused attention epilogue ----------------
// CTA 128x128, BK=32, row stride 144B (36 floats), 2-stage cp.async, 2 CTA/SM.
#define ROWF   144
#define OFFA3  0
#define OFFB3  18432            // 128*144
#define STG3   36864
#define GSMEM3 73728

__device__ __forceinline__ void load_stage3(uint32_t sb, int bm, int bn, int K,
                                            int k0, int tid) {
#pragma unroll
    for (int i = 0; i < 4; i++) {
        int idx = tid + i * 256;
        int row = idx >> 3, seg = idx & 7;
        uint32_t so = row * ROWF + seg * 16;
        cp16(sb + OFFA3 + so, g_Af + (size_t)(bm + row) * K + k0 + seg * 4);
        cp16(sb + OFFB3 + so, g_Bf + (size_t)(bn + row) * K + k0 + seg * 4);
    }
}

__global__ __launch_bounds__(256, 2) void k_gemm_mma(int K,
        const float* __restrict__ asrc, const float* __restrict__ adst) {
    extern __shared__ char smem[];
    uint32_t sb = smem_u32(smem);
    int tid = threadIdx.x, lane = tid & 31, w = tid >> 5;
    int bm = blockIdx.x * 128, bn = blockIdx.y * 128;
    int wm = (w >> 2) * 64, wn = (w & 3) * 32;
    int r4 = lane >> 2, c4 = lane & 3;

    float acc[4][4][4];
#pragma unroll
    for (int mt = 0; mt < 4; mt++)
#pragma unroll
        for (int nt = 0; nt < 4; nt++)
#pragma unroll
            for (int j = 0; j < 4; j++) acc[mt][nt][j] = 0.f;

    uint32_t a_off = (uint32_t)(wm + r4) * ROWF + c4 * 4;
    uint32_t b_off = (uint32_t)(wn + r4) * ROWF + c4 * 4;

    const int nc = K >> 5;
    load_stage3(sb, bm, bn, K, 0, tid);
    CP_COMMIT();

    for (int kc = 0; kc < nc; kc++) {
        if (kc + 1 < nc) {
            load_stage3(sb + ((kc + 1) & 1) * STG3, bm, bn, K, (kc + 1) << 5, tid);
            CP_COMMIT();
            CP_WAIT(1);
        } else {
            CP_WAIT(0);
        }
        __syncthreads();
        const char* st = smem + (kc & 1) * STG3;
#pragma unroll
        for (int s = 0; s < 4; s++) {
            int kb = s * 32;                       // 8 floats per k8 step
            uint32_t a[4][4], b[4][2];
#pragma unroll
            for (int mt = 0; mt < 4; mt++) {
                const char* p = st + OFFA3 + a_off + mt * (16 * ROWF) + kb;
                a[mt][0] = *(const uint32_t*)(p);
                a[mt][1] = *(const uint32_t*)(p + 8 * ROWF);
                a[mt][2] = *(const uint32_t*)(p + 16);
                a[mt][3] = *(const uint32_t*)(p + 8 * ROWF + 16);
            }
#pragma unroll
            for (int nt = 0; nt < 4; nt++) {
                const char* p = st + OFFB3 + b_off + nt * (8 * ROWF) + kb;
                b[nt][0] = *(const uint32_t*)(p);
                b[nt][1] = *(const uint32_t*)(p + 16);
            }
#pragma unroll
            for (int nt = 0; nt < 4; nt++)
#pragma unroll
                for (int mt = 0; mt < 4; mt++)
                    mma_tf32(acc[mt][nt], a[mt], b[nt]);
        }
        __syncthreads();
    }

    // ---- fused epilogue: store g_h tile + per-row attention partial dots ---
    int r = lane >> 2, cq = lane & 3;
    int hh = ((bn + wn) >> 6) & 3;
    float2 as2[4], ad2[4];
#pragma unroll
    for (int nt = 0; nt < 4; nt++) {
        int col = bn + wn + nt * 8 + cq * 2;
        as2[nt] = *(const float2*)(asrc + col);
        ad2[nt] = *(const float2*)(adst + col);
    }
#pragma unroll
    for (int mt = 0; mt < 4; mt++) {
        int row0 = bm + wm + mt * 16 + r;
        float ps0 = 0.f, pd0 = 0.f, ps1 = 0.f, pd1 = 0.f;
#pragma unroll
        for (int nt = 0; nt < 4; nt++) {
            int col = bn + wn + nt * 8 + cq * 2;
            ps0 += acc[mt][nt][0] * as2[nt].x + acc[mt][nt][1] * as2[nt].y;
            pd0 += acc[mt][nt][0] * ad2[nt].x + acc[mt][nt][1] * ad2[nt].y;
            ps1 += acc[mt][nt][2] * as2[nt].x + acc[mt][nt][3] * as2[nt].y;
            pd1 += acc[mt][nt][2] * ad2[nt].x + acc[mt][nt][3] * ad2[nt].y;
            if (row0 < NNODES)
                *(float2*)(g_h + (size_t)row0 * WID + col) =
                    make_float2(acc[mt][nt][0], acc[mt][nt][1]);
            if (row0 + 8 < NNODES)
                *(float2*)(g_h + (size_t)(row0 + 8) * WID + col) =
                    make_float2(acc[mt][nt][2], acc[mt][nt][3]);
        }
        ps0 += __shfl_down_sync(0xffffffffu, ps0, 2);
        ps0 += __shfl_down_sync(0xffffffffu, ps0, 1);
        pd0 += __shfl_down_sync(0xffffffffu, pd0, 2);
        pd0 += __shfl_down_sync(0xffffffffu, pd0, 1);
        ps1 += __shfl_down_sync(0xffffffffu, ps1, 2);
        ps1 += __shfl_down_sync(0xffffffffu, ps1, 1);
        pd1 += __shfl_down_sync(0xffffffffu, pd1, 2);
        pd1 += __shfl_down_sync(0xffffffffu, pd1, 1);
        if (cq == 0) {
            if (row0 < NNODES) {
                atomicAdd(&g_als[row0 * 4 + hh], ps0);
                atomicAdd(&g_ald[row0 * 4 + hh], pd0);
            }
            if (row0 + 8 < NNODES) {
                atomicAdd(&g_als[(row0 + 8) * 4 + hh], ps1);
                atomicAdd(&g_ald[(row0 + 8) * 4 + hh], pd1);
            }
        }
    }
}

// --------- aggregation: WARP per node — no block syncs ---------
// lane owns channels lane*8..lane*8+7; head = lane>>3 (8-lane groups).
__global__ __launch_bounds__(128) void k_aggregate(const float* __restrict__ bias, int dosplit,
        const float* __restrict__ linw, const void* __restrict__ batch, float* out) {
    __shared__ float s_al[4][4][DCAPW];   // [warp][head][edge]
    __shared__ int   s_src[4][DCAPW];
    int wid = threadIdx.x >> 5, lane = threadIdx.x & 31;
    int n = blockIdx.x * 4 + wid;
    int start = g_rowptr[n];
    int deg = g_rowptr[n + 1] - start;
    int g = lane >> 3;
    int j = lane & 7;

    float4 aldn = ((const float4*)g_ald)[n];
    float inv;
    float acc[8];
#pragma unroll
    for (int k = 0; k < 8; k++) acc[k] = 0.f;
    int c = lane * 8;

    if (deg <= DCAPW) {
        for (int i = lane; i < deg; i += 32) {
            int s = g_scsr[start + i];
            s_src[wid][i] = s;
            float4 a = ((const float4*)g_als)[s];
            float t0 = a.x + aldn.x; t0 = t0 > 0.f ? t0 : 0.2f * t0;
            float t1 = a.y + aldn.y; t1 = t1 > 0.f ? t1 : 0.2f * t1;
            float t2 = a.z + aldn.z; t2 = t2 > 0.f ? t2 : 0.2f * t2;
            float t3 = a.w + aldn.w; t3 = t3 > 0.f ? t3 : 0.2f * t3;
            s_al[wid][0][i] = t0; s_al[wid][1][i] = t1;
            s_al[wid][2][i] = t2; s_al[wid][3][i] = t3;
        }
        __syncwarp();

        float mx = -1e30f;
        for (int i = j; i < deg; i += 8) mx = fmaxf(mx, s_al[wid][g][i]);
#pragma unroll
        for (int o = 4; o; o >>= 1) mx = fmaxf(mx, __shfl_xor_sync(0xffffffffu, mx, o));
        float sum = 0.f;
        for (int i = j; i < deg; i += 8) {
            float ex = expf(s_al[wid][g][i] - mx);
            s_al[wid][g][i] = ex;
            sum += ex;
        }
#pragma unroll
        for (int o = 4; o; o >>= 1) sum += __shfl_xor_sync(0xffffffffu, sum, o);
        inv = 1.f / (sum + 1e-16f);
        __syncwarp();

        const float* alp = s_al[wid][g];
        const int*   sp  = s_src[wid];
        float b[8];
#pragma unroll
        for (int k = 0; k < 8; k++) b[k] = 0.f;
        int i = 0;
        for (; i + 2 <= deg; i += 2) {
            float p = alp[i], q = alp[i + 1];
            const float* r0 = g_h + (size_t)sp[i] * WID + c;
            const float* r1 = g_h + (size_t)sp[i + 1] * WID + c;
            float4 u0 = *(const float4*)r0, u1 = *(const float4*)(r0 + 4);
            float4 w0 = *(const float4*)r1, w1 = *(const float4*)(r1 + 4);
            acc[0] += p * u0.x; acc[1] += p * u0.y; acc[2] += p * u0.z; acc[3] += p * u0.w;
            acc[4] += p * u1.x; acc[5] += p * u1.y; acc[6] += p * u1.z; acc[7] += p * u1.w;
            b[0] += q * w0.x; b[1] += q * w0.y; b[2] += q * w0.z; b[3] += q * w0.w;
            b[4] += q * w1.x; b[5] += q * w1.y; b[6] += q * w1.z; b[7] += q * w1.w;
        }
        if (i < deg) {
            float p = alp[i];
            const float* r0 = g_h + (size_t)sp[i] * WID + c;
            float4 u0 = *(const float4*)r0, u1 = *(const float4*)(r0 + 4);
            acc[0] += p * u0.x; acc[1] += p * u0.y; acc[2] += p * u0.z; acc[3] += p * u0.w;
            acc[4] += p * u1.x; acc[5] += p * u1.y; acc[6] += p * u1.z; acc[7] += p * u1.w;
        }
#pragma unroll
        for (int k = 0; k < 8; k++) acc[k] += b[k];
    } else {
        // -------- fallback: deg > DCAPW, warp-local via g_esc ----------
        float4 mx4 = make_float4(-1e30f, -1e30f, -1e30f, -1e30f);
        for (int i = lane; i < deg; i += 32) {
            float4 a = ((const float4*)g_als)[g_scsr[start + i]];
            a.x += aldn.x; a.x = a.x > 0.f ? a.x : 0.2f * a.x;
            a.y += aldn.y; a.y = a.y > 0.f ? a.y : 0.2f * a.y;
            a.z += aldn.z; a.z = a.z > 0.f ? a.z : 0.2f * a.z;
            a.w += aldn.w; a.w = a.w > 0.f ? a.w : 0.2f * a.w;
            ((float4*)g_esc)[start + i] = a;
            mx4.x = fmaxf(mx4.x, a.x); mx4.y = fmaxf(mx4.y, a.y);
            mx4.z = fmaxf(mx4.z, a.z); mx4.w = fmaxf(mx4.w, a.w);
        }
#pragma unroll
        for (int o = 16; o; o >>= 1) {
            mx4.x = fmaxf(mx4.x, __shfl_xor_sync(0xffffffffu, mx4.x, o));
            mx4.y = fmaxf(mx4.y, __shfl_xor_sync(0xffffffffu, mx4.y, o));
            mx4.z = fmaxf(mx4.z, __shfl_xor_sync(0xffffffffu, mx4.z, o));
            mx4.w = fmaxf(mx4.w, __shfl_xor_sync(0xffffffffu, mx4.w, o));
        }
        __threadfence_block();
        __syncwarp();
        float4 sum4 = make_float4(0.f, 0.f, 0.f, 0.f);
        for (int i = lane; i < deg; i += 32) {
            float4 e = ((float4*)g_esc)[start + i];
            e.x = expf(e.x - mx4.x); e.y = expf(e.y - mx4.y);
            e.z = expf(e.z - mx4.z); e.w = expf(e.w - mx4.w);
            ((float4*)g_esc)[start + i] = e;
            sum4.x += e.x; sum4.y += e.y; sum4.z += e.z; sum4.w += e.w;
        }
#pragma unroll
        for (int o = 16; o; o >>= 1) {
            sum4.x += __shfl_xor_sync(0xffffffffu, sum4.x, o);
            sum4.y += __shfl_xor_sync(0xffffffffu, sum4.y, o);
            sum4.z += __shfl_xor_sync(0xffffffffu, sum4.z, o);
            sum4.w += __shfl_xor_sync(0xffffffffu, sum4.w, o);
        }
        float sums[4] = {sum4.x, sum4.y, sum4.z, sum4.w};
        inv = 1.f / (sums[g] + 1e-16f);
        __threadfence_block();
        __syncwarp();
        for (int i = 0; i < deg; i++) {
            float a = g_esc[(size_t)(start + i) * 4 + g];
            const float* r0 = g_h + (size_t)g_scsr[start + i] * WID + c;
            float4 u0 = *(const float4*)r0, u1 = *(const float4*)(r0 + 4);
            acc[0] += a * u0.x; acc[1] += a * u0.y; acc[2] += a * u0.z; acc[3] += a * u0.w;
            acc[4] += a * u1.x; acc[5] += a * u1.y; acc[6] += a * u1.z; acc[7] += a * u1.w;
        }
    }

    // ---- epilogue: bias + ELU, then split (tf32) or pool ----
    float4 b0 = *(const float4*)(bias + c), b1 = *(const float4*)(bias + c + 4);
    float v[8];
    v[0] = acc[0] * inv + b0.x; v[1] = acc[1] * inv + b0.y;
    v[2] = acc[2] * inv + b0.z; v[3] = acc[3] * inv + b0.w;
    v[4] = acc[4] * inv + b1.x; v[5] = acc[5] * inv + b1.y;
    v[6] = acc[6] * inv + b1.z; v[7] = acc[7] * inv + b1.w;
#pragma unroll
    for (int k = 0; k < 8; k++) v[k] = v[k] > 0.f ? v[k] : expm1f(v[k]);

    if (dosplit) {
        float4 o0 = make_float4(to_tf32(v[0]), to_tf32(v[1]), to_tf32(v[2]), to_tf32(v[3]));
        float4 o1 = make_float4(to_tf32(v[4]), to_tf32(v[5]), to_tf32(v[6]), to_tf32(v[7]));
        *(float4*)(g_Af + (size_t)n * WID + c)     = o0;
        *(float4*)(g_Af + (size_t)n * WID + c + 4) = o1;
    } else {
        float4 w0 = *(const float4*)(linw + c), w1 = *(const float4*)(linw + c + 4);
        float part = v[0] * w0.x + v[1] * w0.y + v[2] * w0.z + v[3] * w0.w
                   + v[4] * w1.x + v[5] * w1.y + v[6] * w1.z + v[7] * w1.w;
#pragma unroll
        for (int o = 16; o; o >>= 1) part += __shfl_xor_sync(0xffffffffu, part, o);
        if (lane == 0) {
            int gg = g_i64flag ? (int)((const long long*)batch)[n]
                               : ((const int*)batch)[n];
            atomicAdd(&out[gg], part);
        }
    }
}

// ---------------- launch ----------------
extern "C" void kernel_launch(void* const* d_in, const int* in_sizes, int n_in,
                              void* d_out, int out_size) {
    const float* x     = (const float*)d_in[0];
    const void*  ei    = d_in[1];
    const void*  batch = d_in[3];
    const float* W[3]    = {(const float*)d_in[4],  (const float*)d_in[8],  (const float*)d_in[12]};
    const float* asrc[3] = {(const float*)d_in[5],  (const float*)d_in[9],  (const float*)d_in[13]};
    const float* adst[3] = {(const float*)d_in[6],  (const float*)d_in[10], (const float*)d_in[14]};
    const float* bb[3]   = {(const float*)d_in[7],  (const float*)d_in[11], (const float*)d_in[15]};
    const float* linw = (const float*)d_in[16];
    const float* linb = (const float*)d_in[17];
    float* out = (float*)d_out;

    static int smem_set = 0;
    if (!smem_set) {
        cudaFuncSetAttribute(k_gemm_mma, cudaFuncAttributeMaxDynamicSharedMemorySize, GSMEM3);
        smem_set = 1;
    }

    dim3 ggrid(MTILES, 2);
    int nodeGrid = (NNODES + 255) / 256;
    int aggGrid = NNODES / 4;   // 12500

    // probe + clear, layer-0 tf32 round (also zeroes g_als/ald), W0, GEMM0
    k_probe_clear<<<nodeGrid, 256>>>((const int*)ei);
    k_splitA<<<(NNODES * 128 / 4 + 255) / 256, 256>>>(x, NNODES * 128 / 4);
    k_splitW0<<<(128 * WID + 255) / 256, 256>>>(W[0], 128);
    k_gemm_mma<<<ggrid, 256, GSMEM3>>>(128, asrc[0], adst[0]);

    // CSR build (before first aggregate)
    k_count<<<(ETOT + 255) / 256, 256>>>(ei);
    int nb = (NNODES + 1023) / 1024;
    k_scan_blk<<<nb, 1024>>>();
    k_scan_top<<<1, 64>>>(nb);
    k_scan_fix<<<nodeGrid, 256>>>();
    k_fill<<<(ETOT + 255) / 256, 256>>>();

    // layer 0 tail
    k_aggregate<<<aggGrid, 128>>>(bb[0], 1, nullptr, nullptr, nullptr);

    // layer 1 (K=256); splitW also clears g_als/ald
    k_splitW<<<(256 * WID + 255) / 256, 256>>>(W[1], 256, nullptr, nullptr);
    k_gemm_mma<<<ggrid, 256, GSMEM3>>>(256, asrc[1], adst[1]);
    k_aggregate<<<aggGrid, 128>>>(bb[1], 1, nullptr, nullptr, nullptr);

    // layer 2 (K=256): splitW also inits out; aggregate fuses pooling + head
    k_splitW<<<(256 * WID + 255) / 256, 256>>>(W[2], 256, out, linb);
    k_gemm_mma<<<ggrid, 256, GSMEM3>>>(256, asrc[2], adst[2]);
    k_aggregate<<<aggGrid, 128>>>(bb[2], 0, linw, batch, out);
}